// round 12
// baseline (speedup 1.0000x reference)
#include <cuda_runtime.h>
#include <cuda_fp16.h>
#include <cstdint>
#include <cstddef>

#define N_NEWS 100000
#define N_ENT  50000
#define N_TOP  2000
#define DIM    128
#define KDIM   384   // 3*DIM
#define HIDN   512
#define OUTD   128
#define MAX_EDGES 1600000
#define NTOT2  (2 * N_NEWS)

// ---------------- scratch (__device__ globals: allocation-free rule) -------
// g_cnt is zero at module load; scan_all re-zeroes it every run (replay-safe).
__device__ int g_cnt[NTOT2];
__device__ int g_deg[NTOT2];
__device__ int g_rowstart[NTOT2];
__device__ int g_cursor[NTOT2];
__device__ int g_csr_col[2 * MAX_EDGES];

__device__ __half g_entf16[(size_t)N_ENT * DIM];
__device__ __half g_topf16[(size_t)N_TOP * DIM];

__device__ __half g_X[(size_t)N_NEWS * KDIM];
__device__ __half g_W1t[(size_t)HIDN * KDIM];   // [N=512][K=384]
__device__ __half g_W2t[(size_t)OUTD * HIDN];   // [N=128][K=512]

// ---------------- helpers --------------------------------------------------
__device__ __forceinline__ uint32_t smem_to_u32(const void* p) {
    uint32_t a;
    asm("{ .reg .u64 t; cvta.to.shared.u64 t, %1; cvt.u32.u64 %0, t; }"
        : "=r"(a) : "l"(p));
    return a;
}

__device__ __forceinline__ void ldsm_x4(uint32_t* r, uint32_t addr) {
    asm volatile("ldmatrix.sync.aligned.m8n8.x4.shared.b16 {%0,%1,%2,%3}, [%4];"
                 : "=r"(r[0]), "=r"(r[1]), "=r"(r[2]), "=r"(r[3]) : "r"(addr));
}
__device__ __forceinline__ void mma_fp16(float* d, const uint32_t* a,
                                         const uint32_t* b) {
    asm volatile(
        "mma.sync.aligned.m16n8k16.row.col.f32.f16.f16.f32 "
        "{%0,%1,%2,%3}, {%4,%5,%6,%7}, {%8,%9}, {%0,%1,%2,%3};"
        : "+f"(d[0]), "+f"(d[1]), "+f"(d[2]), "+f"(d[3])
        : "r"(a[0]), "r"(a[1]), "r"(a[2]), "r"(a[3]), "r"(b[0]), "r"(b[1]));
}

__device__ __forceinline__ void cpa16(uint32_t s, const void* g, int valid) {
    asm volatile("cp.async.cg.shared.global [%0], [%1], 16, %2;"
                 :: "r"(s), "l"(g), "r"(valid ? 16 : 0) : "memory");
}
#define CP_COMMIT() asm volatile("cp.async.commit_group;" ::: "memory")
#define CP_WAIT(n)  asm volatile("cp.async.wait_group %0;" :: "n"(n) : "memory")

// swizzled byte offset inside a [128 rows x 128B] tile
__device__ __forceinline__ uint32_t sw_off(int row, int chunk16) {
    return (uint32_t)row * 128u + (uint32_t)((chunk16 ^ (row & 7)) << 4);
}

// ==================== launch 1: setup ======================================
__global__ void setup_kernel(const float* __restrict__ W1,
                             const float* __restrict__ W2,
                             const int* __restrict__ ent_row, int n_ent,
                             const int* __restrict__ top_row, int n_top,
                             const float* __restrict__ entf,
                             const float* __restrict__ topf,
                             int b1e, int b2e, int bhe, int bte, int bfe) {
    int b = blockIdx.x;
    if (b < b1e) {
        int idx = b * 256 + threadIdx.x;
        if (idx < KDIM * HIDN) {
            int k = idx / HIDN, n = idx - k * HIDN;
            g_W1t[(size_t)n * KDIM + k] = __float2half_rn(W1[idx]);
        }
    } else if (b < b2e) {
        int idx = (b - b1e) * 256 + threadIdx.x;
        if (idx < HIDN * OUTD) {
            int k = idx / OUTD, n = idx - k * OUTD;
            g_W2t[(size_t)n * HIDN + k] = __float2half_rn(W2[idx]);
        }
    } else if (b < bhe) {
        int i = (b - b2e) * 256 + threadIdx.x;
        if (i < n_ent) atomicAdd(&g_cnt[ent_row[i]], 1);
    } else if (b < bte) {
        int i = (b - bhe) * 256 + threadIdx.x;
        if (i < n_top) atomicAdd(&g_cnt[N_NEWS + top_row[i]], 1);
    } else if (b < bfe) {
        size_t i = ((size_t)(b - bte) * 256 + threadIdx.x) * 8;
        if (i < (size_t)N_ENT * DIM) {
            float4 f0 = *reinterpret_cast<const float4*>(entf + i);
            float4 f1 = *reinterpret_cast<const float4*>(entf + i + 4);
            __half h[8];
            h[0] = __float2half_rn(f0.x); h[1] = __float2half_rn(f0.y);
            h[2] = __float2half_rn(f0.z); h[3] = __float2half_rn(f0.w);
            h[4] = __float2half_rn(f1.x); h[5] = __float2half_rn(f1.y);
            h[6] = __float2half_rn(f1.z); h[7] = __float2half_rn(f1.w);
            *reinterpret_cast<uint4*>(&g_entf16[i]) = *reinterpret_cast<uint4*>(h);
        }
    } else {
        size_t i = ((size_t)(b - bfe) * 256 + threadIdx.x) * 8;
        if (i < (size_t)N_TOP * DIM) {
            float4 f0 = *reinterpret_cast<const float4*>(topf + i);
            float4 f1 = *reinterpret_cast<const float4*>(topf + i + 4);
            __half h[8];
            h[0] = __float2half_rn(f0.x); h[1] = __float2half_rn(f0.y);
            h[2] = __float2half_rn(f0.z); h[3] = __float2half_rn(f0.w);
            h[4] = __float2half_rn(f1.x); h[5] = __float2half_rn(f1.y);
            h[6] = __float2half_rn(f1.z); h[7] = __float2half_rn(f1.w);
            *reinterpret_cast<uint4*>(&g_topf16[i]) = *reinterpret_cast<uint4*>(h);
        }
    }
}

// ==================== launch 2: single-block scan ==========================
__global__ void scan_all_kernel() {
    __shared__ int wsum[32];
    __shared__ int carry_sh;
    const int t = threadIdx.x;
    const int lane = t & 31, wid = t >> 5;
    if (t == 0) carry_sh = 0;
    __syncthreads();
    for (int base = 0; base < NTOT2; base += 1024) {
        int i = base + t;
        int v = (i < NTOT2) ? g_cnt[i] : 0;
        if (i < NTOT2) { g_deg[i] = v; g_cnt[i] = 0; }
        int incl = v;
        #pragma unroll
        for (int off = 1; off < 32; off <<= 1) {
            int x = __shfl_up_sync(0xFFFFFFFF, incl, off);
            if (lane >= off) incl += x;
        }
        if (lane == 31) wsum[wid] = incl;
        __syncthreads();
        if (wid == 0) {
            int s = wsum[lane];
            int si = s;
            #pragma unroll
            for (int off = 1; off < 32; off <<= 1) {
                int x = __shfl_up_sync(0xFFFFFFFF, si, off);
                if (lane >= off) si += x;
            }
            wsum[lane] = si - s;
        }
        __syncthreads();
        int carry = carry_sh;
        int excl = carry + wsum[wid] + (incl - v);
        if (i < NTOT2) { g_rowstart[i] = excl; g_cursor[i] = excl; }
        __syncthreads();
        if (t == 1023) carry_sh = excl + v;
        __syncthreads();
    }
}

// ==================== launch 3: fill both edge lists =======================
__global__ void fill_both_kernel(const int* __restrict__ ent_row,
                                 const int* __restrict__ ent_col, int n_ent,
                                 const int* __restrict__ top_row,
                                 const int* __restrict__ top_col, int n_top,
                                 int be) {
    int b = blockIdx.x;
    if (b < be) {
        int i = b * 256 + threadIdx.x;
        if (i < n_ent) {
            int p = atomicAdd(&g_cursor[ent_row[i]], 1);
            g_csr_col[p] = ent_col[i];
        }
    } else {
        int i = (b - be) * 256 + threadIdx.x;
        if (i < n_top) {
            int p = atomicAdd(&g_cursor[N_NEWS + top_row[i]], 1);
            g_csr_col[p] = top_col[i];
        }
    }
}

// ==================== launch 4: gather (one warp per news row) =============
__device__ __forceinline__ void store_h4(int r, int colb, float4 v) {
    __half h[4];
    h[0] = __float2half_rn(v.x);
    h[1] = __float2half_rn(v.y);
    h[2] = __float2half_rn(v.z);
    h[3] = __float2half_rn(v.w);
    *reinterpret_cast<uint2*>(&g_X[(size_t)r * KDIM + colb]) =
        *reinterpret_cast<uint2*>(h);
}

__device__ __forceinline__ void agg_part16(const __half* __restrict__ feats,
                                           int s, int c, int r, int colb,
                                           int lane) {
    float a0 = 0.f, a1 = 0.f, a2 = 0.f, a3 = 0.f;
    float b0 = 0.f, b1 = 0.f, b2 = 0.f, b3 = 0.f;
    const uint2* f2 = reinterpret_cast<const uint2*>(feats);
    int j = 0;
    for (; j + 2 <= c; j += 2) {
        int c0 = g_csr_col[s + j];
        int c1 = g_csr_col[s + j + 1];
        uint2 u0 = f2[(size_t)c0 * 32 + lane];
        uint2 u1 = f2[(size_t)c1 * 32 + lane];
        float2 p0 = __half22float2(*reinterpret_cast<__half2*>(&u0.x));
        float2 p1 = __half22float2(*reinterpret_cast<__half2*>(&u0.y));
        float2 q0 = __half22float2(*reinterpret_cast<__half2*>(&u1.x));
        float2 q1 = __half22float2(*reinterpret_cast<__half2*>(&u1.y));
        a0 += p0.x; a1 += p0.y; a2 += p1.x; a3 += p1.y;
        b0 += q0.x; b1 += q0.y; b2 += q1.x; b3 += q1.y;
    }
    if (j < c) {
        int c0 = g_csr_col[s + j];
        uint2 u0 = f2[(size_t)c0 * 32 + lane];
        float2 p0 = __half22float2(*reinterpret_cast<__half2*>(&u0.x));
        float2 p1 = __half22float2(*reinterpret_cast<__half2*>(&u0.y));
        a0 += p0.x; a1 += p0.y; a2 += p1.x; a3 += p1.y;
    }
    float inv = 1.0f / ((float)c + 1e-8f);
    float4 v = make_float4((a0 + b0) * inv, (a1 + b1) * inv,
                           (a2 + b2) * inv, (a3 + b3) * inv);
    store_h4(r, colb, v);
}

__global__ __launch_bounds__(256) void gather_kernel(
    const float* __restrict__ news) {
    int gw   = (blockIdx.x * blockDim.x + threadIdx.x) >> 5;
    int lane = threadIdx.x & 31;
    if (gw >= N_NEWS) return;
    float4 v = reinterpret_cast<const float4*>(news)[(size_t)gw * 32 + lane];
    store_h4(gw, lane * 4, v);
    agg_part16(g_entf16, g_rowstart[gw], g_deg[gw], gw, 128 + lane * 4, lane);
    agg_part16(g_topf16, g_rowstart[N_NEWS + gw], g_deg[N_NEWS + gw], gw,
               256 + lane * 4, lane);
}

// ==================== launch 5: fused MLP ==================================
// Per CTA (128 M-rows): H = tanh(X@W1t^T + b1) built in smem (fp16, 4 n-passes),
// then out = H @ W2t^T + b2 streamed to global. 256 threads, 1 CTA/SM.
// smem: H 128x512 fp16 (1024B rows, XOR-swizzled) + 2-stage A/B staging.
#define TILE_BYTES 16384
#define SM_H_BYTES (128 * 1024)                  // 131072
#define SM_STAGE   SM_H_BYTES
#define FUSED_SMEM (SM_H_BYTES + 4 * TILE_BYTES) // 196608

// H smem byte offset for (row 0..127, col 0..511)
__device__ __forceinline__ uint32_t h_off(int row, int col) {
    uint32_t group = (uint32_t)(col >> 6);            // 128B group
    uint32_t c = (uint32_t)((col >> 3) & 7);
    return (uint32_t)row * 1024u + group * 128u +
           ((c ^ (uint32_t)(row & 7)) << 4) + (uint32_t)((col & 7) * 2);
}

__global__ __launch_bounds__(256, 1) void fused_mlp_kernel(
    const __half* __restrict__ X, const __half* __restrict__ W1t,
    const __half* __restrict__ W2t,
    const float* __restrict__ b1, const float* __restrict__ b2,
    float* __restrict__ out, int M) {
    extern __shared__ __align__(1024) char smem[];
    const uint32_t sbase = smem_to_u32(smem);
    const uint32_t sH = sbase;
    const uint32_t sStage = sbase + SM_STAGE;

    const int tid  = threadIdx.x;
    const int wid  = tid >> 5;
    const int lane = tid & 31;
    const int wm   = wid & 1;
    const int wn   = wid >> 1;
    const int m0   = blockIdx.x * 128;

    const int lrow = tid >> 1;
    const int lseg = (tid & 1) * 4;
    const int gr   = m0 + lrow;
    const int a_ok = gr < M;
    const size_t xa_base = (size_t)gr * KDIM + lseg * 8;

    const int a_row = (lane & 7) + ((lane >> 3) & 1) * 8;
    const int a_ch  = lane >> 4;
    const int b_row = (lane & 7) + ((lane >> 4) & 1) * 8;
    const int b_ch  = (lane >> 3) & 1;

    const int g = lane >> 2;
    const int q = lane & 3;

    // ---------------- phase 1: H = tanh(X @ W1^T + b1), 4 n-passes --------
    for (int pass = 0; pass < 4; pass++) {
        float acc[4][4][4] = {};
        const size_t w1_base =
            (size_t)(pass * 128 + lrow) * KDIM + lseg * 8;

        auto prefetch1 = [&](int ch) {
            const int k0 = ch << 6;
            const uint32_t sb = sStage + (ch & 1) * (2 * TILE_BYTES);
            const __half* pa = X + xa_base + k0;
            const __half* pb = W1t + w1_base + k0;
            #pragma unroll
            for (int s = 0; s < 4; s++) {
                uint32_t so = sw_off(lrow, lseg + s);
                cpa16(sb + so,              pa + s * 8, a_ok);
                cpa16(sb + TILE_BYTES + so, pb + s * 8, 1);
            }
            CP_COMMIT();
        };

        prefetch1(0);
        const int n_chunks = KDIM >> 6;  // 6
        for (int ch = 0; ch < n_chunks; ch++) {
            if (ch + 1 < n_chunks) {
                prefetch1(ch + 1);
                CP_WAIT(1);
            } else {
                CP_WAIT(0);
            }
            __syncthreads();
            const uint32_t st = sStage + (ch & 1) * (2 * TILE_BYTES);
            #pragma unroll
            for (int kk = 0; kk < 4; kk++) {
                uint32_t afrag[4][4];
                uint32_t bhf[2][4];
                #pragma unroll
                for (int g2 = 0; g2 < 2; g2++) {
                    int nr = wn * 32 + g2 * 16 + b_row;
                    ldsm_x4(bhf[g2], st + TILE_BYTES + sw_off(nr, 2 * kk + b_ch));
                }
                #pragma unroll
                for (int mi = 0; mi < 4; mi++) {
                    int mr = wm * 64 + mi * 16 + a_row;
                    ldsm_x4(afrag[mi], st + sw_off(mr, 2 * kk + a_ch));
                }
                #pragma unroll
                for (int mi = 0; mi < 4; mi++)
                    #pragma unroll
                    for (int ni = 0; ni < 4; ni++)
                        mma_fp16(acc[mi][ni], afrag[mi],
                                 &bhf[ni >> 1][(ni & 1) * 2]);
            }
            __syncthreads();
        }

        // epilogue: tanh + bias -> H smem (fp16)
        #pragma unroll
        for (int mi = 0; mi < 4; mi++) {
            #pragma unroll
            for (int ni = 0; ni < 4; ni++) {
                int colw = wn * 32 + ni * 8 + q * 2;       // within pass
                int col = pass * 128 + colw;
                float bia0 = b1[col], bia1 = b1[col + 1];
                #pragma unroll
                for (int hf = 0; hf < 2; hf++) {
                    int row = wm * 64 + mi * 16 + g + hf * 8;
                    float v0 = tanhf(acc[mi][ni][hf * 2 + 0] + bia0);
                    float v1 = tanhf(acc[mi][ni][hf * 2 + 1] + bia1);
                    uint32_t ho = h_off(row, col);
                    __half2 hv = __halves2half2(__float2half_rn(v0),
                                                __float2half_rn(v1));
                    *reinterpret_cast<__half2*>(smem + ho) = hv;
                }
            }
        }
        // next pass's prefetch reuses staging; reads of it finished at the
        // loop-end __syncthreads(). H writes are per-thread disjoint.
    }
    __syncthreads();  // H complete, visible to all warps

    // ---------------- phase 2: out = H @ W2^T + b2 ------------------------
    {
        float acc[4][4][4] = {};
        const size_t w2_base = (size_t)lrow * HIDN + lseg * 8;

        auto prefetch2 = [&](int ch) {
            const int k0 = ch << 6;
            const uint32_t sb = sStage + (ch & 1) * (2 * TILE_BYTES) + TILE_BYTES;
            const __half* pb = W2t + w2_base + k0;
            #pragma unroll
            for (int s = 0; s < 4; s++) {
                uint32_t so = sw_off(lrow, lseg + s);
                cpa16(sb + so, pb + s * 8, 1);
            }
            CP_COMMIT();
        };

        prefetch2(0);
        const int n_chunks = HIDN >> 6;  // 8
        for (int ch = 0; ch < n_chunks; ch++) {
            if (ch + 1 < n_chunks) {
                prefetch2(ch + 1);
                CP_WAIT(1);
            } else {
                CP_WAIT(0);
            }
            __syncthreads();
            const uint32_t st = sStage + (ch & 1) * (2 * TILE_BYTES) + TILE_BYTES;
            #pragma unroll
            for (int kk = 0; kk < 4; kk++) {
                uint32_t afrag[4][4];
                uint32_t bhf[2][4];
                #pragma unroll
                for (int g2 = 0; g2 < 2; g2++) {
                    int nr = wn * 32 + g2 * 16 + b_row;
                    ldsm_x4(bhf[g2], st + sw_off(nr, 2 * kk + b_ch));
                }
                #pragma unroll
                for (int mi = 0; mi < 4; mi++) {
                    int mr = wm * 64 + mi * 16 + a_row;
                    int c = 2 * kk + a_ch;
                    uint32_t ao = (uint32_t)mr * 1024u + (uint32_t)(ch << 7) +
                                  (uint32_t)((c ^ (mr & 7)) << 4);
                    ldsm_x4(afrag[mi], sH + ao);
                }
                #pragma unroll
                for (int mi = 0; mi < 4; mi++)
                    #pragma unroll
                    for (int ni = 0; ni < 4; ni++)
                        mma_fp16(acc[mi][ni], afrag[mi],
                                 &bhf[ni >> 1][(ni & 1) * 2]);
            }
            __syncthreads();
        }

        // epilogue: bias -> global fp32
        #pragma unroll
        for (int mi = 0; mi < 4; mi++) {
            #pragma unroll
            for (int ni = 0; ni < 4; ni++) {
                int col = wn * 32 + ni * 8 + q * 2;
                float bia0 = b2[col], bia1 = b2[col + 1];
                #pragma unroll
                for (int hf = 0; hf < 2; hf++) {
                    int gm = m0 + wm * 64 + mi * 16 + g + hf * 8;
                    if (gm >= M) continue;
                    float v0 = acc[mi][ni][hf * 2 + 0] + bia0;
                    float v1 = acc[mi][ni][hf * 2 + 1] + bia1;
                    *reinterpret_cast<float2*>(&out[(size_t)gm * OUTD + col]) =
                        make_float2(v0, v1);
                }
            }
        }
    }
}

// ---------------------------------------------------------------------------
extern "C" void kernel_launch(void* const* d_in, const int* in_sizes, int n_in,
                              void* d_out, int out_size) {
    const float* news    = (const float*)d_in[0];
    const float* entf    = (const float*)d_in[1];
    const float* topf    = (const float*)d_in[2];
    const int*   ent_row = (const int*)d_in[3];
    const int*   ent_col = (const int*)d_in[4];
    const int*   top_row = (const int*)d_in[5];
    const int*   top_col = (const int*)d_in[6];
    const float* W1      = (const float*)d_in[7];
    const float* b1      = (const float*)d_in[8];
    const float* W2      = (const float*)d_in[9];
    const float* b2      = (const float*)d_in[10];
    float* out = (float*)d_out;
    int n_ent = in_sizes[3];
    int n_top = in_sizes[5];

    void *p_x, *p_w1, *p_w2;
    cudaGetSymbolAddress(&p_x, g_X);
    cudaGetSymbolAddress(&p_w1, g_W1t);
    cudaGetSymbolAddress(&p_w2, g_W2t);

    cudaFuncSetAttribute(fused_mlp_kernel,
                         cudaFuncAttributeMaxDynamicSharedMemorySize, FUSED_SMEM);

    // launch 1: setup (weight prep + hists + fp16 feature conversion)
    {
        int b1e = (KDIM * HIDN + 255) / 256;
        int b2e = b1e + (HIDN * OUTD + 255) / 256;
        int bhe = b2e + (n_ent + 255) / 256;
        int bte = bhe + (n_top + 255) / 256;
        int bfe = bte + (N_ENT * DIM / 8 + 255) / 256;
        int btot = bfe + (N_TOP * DIM / 8 + 255) / 256;
        setup_kernel<<<btot, 256>>>(W1, W2, ent_row, n_ent, top_row, n_top,
                                    entf, topf, b1e, b2e, bhe, bte, bfe);
    }
    // launch 2: scan
    scan_all_kernel<<<1, 1024>>>();
    // launch 3: fill
    {
        int be = (n_ent + 255) / 256;
        int btot = be + (n_top + 255) / 256;
        fill_both_kernel<<<btot, 256>>>(ent_row, ent_col, n_ent,
                                        top_row, top_col, n_top, be);
    }
    // launch 4: gather -> X (fp16)
    {
        int blocks = (N_NEWS * 32 + 255) / 256;
        gather_kernel<<<blocks, 256>>>(news);
    }
    // launch 5: fused MLP (GEMM1 + tanh + GEMM2)
    {
        int m_tiles = (N_NEWS + 127) / 128;  // 782
        fused_mlp_kernel<<<m_tiles, 256, FUSED_SMEM>>>(
            (const __half*)p_x, (const __half*)p_w1, (const __half*)p_w2,
            b1, b2, out, N_NEWS);
    }
}

// round 13
// speedup vs baseline: 1.4715x; 1.4715x over previous
#include <cuda_runtime.h>
#include <cuda_fp16.h>
#include <cstdint>
#include <cstddef>

#define N_NEWS 100000
#define N_ENT  50000
#define N_TOP  2000
#define DIM    128
#define KDIM   384   // 3*DIM
#define HIDN   512
#define OUTD   128
#define MAX_EDGES 1600000
#define NTOT2  (2 * N_NEWS)
#define SCAN_BLOCKS ((NTOT2 + 1023) / 1024)   // 196

// ---------------- scratch (__device__ globals: allocation-free rule) -------
// g_cnt is zero at module load; scan3 re-zeroes it every run (replay-safe).
__device__ int g_cnt[NTOT2];
__device__ int g_deg[NTOT2];
__device__ int g_rowstart[NTOT2];
__device__ int g_cursor[NTOT2];
__device__ int g_bsum[256];
__device__ int g_csr_col[2 * MAX_EDGES];

__device__ __half g_entf16[(size_t)N_ENT * DIM];
__device__ __half g_topf16[(size_t)N_TOP * DIM];

__device__ __half g_X[(size_t)N_NEWS * KDIM];
__device__ __half g_H[(size_t)N_NEWS * HIDN];
__device__ __half g_W1t[(size_t)HIDN * KDIM];   // [N=512][K=384]
__device__ __half g_W2t[(size_t)OUTD * HIDN];   // [N=128][K=512]

// ---------------- helpers --------------------------------------------------
__device__ __forceinline__ uint32_t smem_to_u32(const void* p) {
    uint32_t a;
    asm("{ .reg .u64 t; cvta.to.shared.u64 t, %1; cvt.u32.u64 %0, t; }"
        : "=r"(a) : "l"(p));
    return a;
}

__device__ __forceinline__ void ldsm_x4(uint32_t* r, uint32_t addr) {
    asm volatile("ldmatrix.sync.aligned.m8n8.x4.shared.b16 {%0,%1,%2,%3}, [%4];"
                 : "=r"(r[0]), "=r"(r[1]), "=r"(r[2]), "=r"(r[3]) : "r"(addr));
}
__device__ __forceinline__ void mma_fp16(float* d, const uint32_t* a,
                                         const uint32_t* b) {
    asm volatile(
        "mma.sync.aligned.m16n8k16.row.col.f32.f16.f16.f32 "
        "{%0,%1,%2,%3}, {%4,%5,%6,%7}, {%8,%9}, {%0,%1,%2,%3};"
        : "+f"(d[0]), "+f"(d[1]), "+f"(d[2]), "+f"(d[3])
        : "r"(a[0]), "r"(a[1]), "r"(a[2]), "r"(a[3]), "r"(b[0]), "r"(b[1]));
}

__device__ __forceinline__ void cpa16(uint32_t s, const void* g, int valid) {
    asm volatile("cp.async.cg.shared.global [%0], [%1], 16, %2;"
                 :: "r"(s), "l"(g), "r"(valid ? 16 : 0) : "memory");
}
#define CP_COMMIT() asm volatile("cp.async.commit_group;" ::: "memory")
#define CP_WAIT(n)  asm volatile("cp.async.wait_group %0;" :: "n"(n) : "memory")

// swizzled byte offset inside a [128 rows x 128B] tile
__device__ __forceinline__ uint32_t sw_off(int row, int chunk16) {
    return (uint32_t)row * 128u + (uint32_t)((chunk16 ^ (row & 7)) << 4);
}

// ==================== launch 1: setup ======================================
__global__ void setup_kernel(const float* __restrict__ W1,
                             const float* __restrict__ W2,
                             const int* __restrict__ ent_row, int n_ent,
                             const int* __restrict__ top_row, int n_top,
                             const float* __restrict__ entf,
                             const float* __restrict__ topf,
                             int b1e, int b2e, int bhe, int bte, int bfe) {
    int b = blockIdx.x;
    if (b < b1e) {
        int idx = b * 256 + threadIdx.x;
        if (idx < KDIM * HIDN) {
            int k = idx / HIDN, n = idx - k * HIDN;
            g_W1t[(size_t)n * KDIM + k] = __float2half_rn(W1[idx]);
        }
    } else if (b < b2e) {
        int idx = (b - b1e) * 256 + threadIdx.x;
        if (idx < HIDN * OUTD) {
            int k = idx / OUTD, n = idx - k * OUTD;
            g_W2t[(size_t)n * HIDN + k] = __float2half_rn(W2[idx]);
        }
    } else if (b < bhe) {
        int i = (b - b2e) * 256 + threadIdx.x;
        if (i < n_ent) atomicAdd(&g_cnt[ent_row[i]], 1);
    } else if (b < bte) {
        int i = (b - bhe) * 256 + threadIdx.x;
        if (i < n_top) atomicAdd(&g_cnt[N_NEWS + top_row[i]], 1);
    } else if (b < bfe) {
        size_t i = ((size_t)(b - bte) * 256 + threadIdx.x) * 8;
        if (i < (size_t)N_ENT * DIM) {
            float4 f0 = *reinterpret_cast<const float4*>(entf + i);
            float4 f1 = *reinterpret_cast<const float4*>(entf + i + 4);
            __half h[8];
            h[0] = __float2half_rn(f0.x); h[1] = __float2half_rn(f0.y);
            h[2] = __float2half_rn(f0.z); h[3] = __float2half_rn(f0.w);
            h[4] = __float2half_rn(f1.x); h[5] = __float2half_rn(f1.y);
            h[6] = __float2half_rn(f1.z); h[7] = __float2half_rn(f1.w);
            *reinterpret_cast<uint4*>(&g_entf16[i]) = *reinterpret_cast<uint4*>(h);
        }
    } else {
        size_t i = ((size_t)(b - bfe) * 256 + threadIdx.x) * 8;
        if (i < (size_t)N_TOP * DIM) {
            float4 f0 = *reinterpret_cast<const float4*>(topf + i);
            float4 f1 = *reinterpret_cast<const float4*>(topf + i + 4);
            __half h[8];
            h[0] = __float2half_rn(f0.x); h[1] = __float2half_rn(f0.y);
            h[2] = __float2half_rn(f0.z); h[3] = __float2half_rn(f0.w);
            h[4] = __float2half_rn(f1.x); h[5] = __float2half_rn(f1.y);
            h[6] = __float2half_rn(f1.z); h[7] = __float2half_rn(f1.w);
            *reinterpret_cast<uint4*>(&g_topf16[i]) = *reinterpret_cast<uint4*>(h);
        }
    }
}

// ==================== launches 2-4: parallel scan ==========================
// scan1: per-block exclusive scan of g_cnt (4 elems/thread), saves deg,
//        writes block sums. 196 blocks x 256 thr.
__global__ void scan1_kernel() {
    __shared__ int sh[256];
    int t = threadIdx.x, b = blockIdx.x;
    int base = b * 1024 + t * 4;
    int v0 = 0, v1 = 0, v2 = 0, v3 = 0;
    if (base + 0 < NTOT2) { v0 = g_cnt[base + 0]; g_deg[base + 0] = v0; }
    if (base + 1 < NTOT2) { v1 = g_cnt[base + 1]; g_deg[base + 1] = v1; }
    if (base + 2 < NTOT2) { v2 = g_cnt[base + 2]; g_deg[base + 2] = v2; }
    if (base + 3 < NTOT2) { v3 = g_cnt[base + 3]; g_deg[base + 3] = v3; }
    sh[t] = v0 + v1 + v2 + v3;
    __syncthreads();
    #pragma unroll
    for (int off = 1; off < 256; off <<= 1) {
        int x = 0;
        if (t >= off) x = sh[t - off];
        __syncthreads();
        if (t >= off) sh[t] += x;
        __syncthreads();
    }
    int run = (t > 0) ? sh[t - 1] : 0;
    if (base + 0 < NTOT2) g_rowstart[base + 0] = run; run += v0;
    if (base + 1 < NTOT2) g_rowstart[base + 1] = run; run += v1;
    if (base + 2 < NTOT2) g_rowstart[base + 2] = run; run += v2;
    if (base + 3 < NTOT2) g_rowstart[base + 3] = run;
    if (t == 255) g_bsum[b] = sh[255];
}

// scan2: single block scans block sums (exclusive, in place)
__global__ void scan2_kernel(int nb) {
    __shared__ int sh[256];
    int t = threadIdx.x;
    int v = (t < nb) ? g_bsum[t] : 0;
    sh[t] = v;
    __syncthreads();
    #pragma unroll
    for (int off = 1; off < 256; off <<= 1) {
        int x = 0;
        if (t >= off) x = sh[t - off];
        __syncthreads();
        if (t >= off) sh[t] += x;
        __syncthreads();
    }
    if (t < nb) g_bsum[t] = (t > 0) ? sh[t - 1] : 0;
}

// scan3: add block offsets, init cursors, re-zero g_cnt (replay invariant)
__global__ void scan3_kernel() {
    int i = blockIdx.x * blockDim.x + threadIdx.x;
    if (i < NTOT2) {
        int v = g_rowstart[i] + g_bsum[i >> 10];
        g_rowstart[i] = v;
        g_cursor[i] = v;
        g_cnt[i] = 0;
    }
}

// ==================== launch 5: fill both edge lists =======================
__global__ void fill_both_kernel(const int* __restrict__ ent_row,
                                 const int* __restrict__ ent_col, int n_ent,
                                 const int* __restrict__ top_row,
                                 const int* __restrict__ top_col, int n_top,
                                 int be) {
    int b = blockIdx.x;
    if (b < be) {
        int i = b * 256 + threadIdx.x;
        if (i < n_ent) {
            int p = atomicAdd(&g_cursor[ent_row[i]], 1);
            g_csr_col[p] = ent_col[i];
        }
    } else {
        int i = (b - be) * 256 + threadIdx.x;
        if (i < n_top) {
            int p = atomicAdd(&g_cursor[N_NEWS + top_row[i]], 1);
            g_csr_col[p] = top_col[i];
        }
    }
}

// ==================== launch 6: gather (one warp per news row) =============
__device__ __forceinline__ void store_h4(int r, int colb, float4 v) {
    __half h[4];
    h[0] = __float2half_rn(v.x);
    h[1] = __float2half_rn(v.y);
    h[2] = __float2half_rn(v.z);
    h[3] = __float2half_rn(v.w);
    *reinterpret_cast<uint2*>(&g_X[(size_t)r * KDIM + colb]) =
        *reinterpret_cast<uint2*>(h);
}

__device__ __forceinline__ void agg_part16(const __half* __restrict__ feats,
                                           int s, int c, int r, int colb,
                                           int lane) {
    float a0 = 0.f, a1 = 0.f, a2 = 0.f, a3 = 0.f;
    float b0 = 0.f, b1 = 0.f, b2 = 0.f, b3 = 0.f;
    const uint2* f2 = reinterpret_cast<const uint2*>(feats);
    int j = 0;
    for (; j + 2 <= c; j += 2) {
        int c0 = g_csr_col[s + j];
        int c1 = g_csr_col[s + j + 1];
        uint2 u0 = f2[(size_t)c0 * 32 + lane];
        uint2 u1 = f2[(size_t)c1 * 32 + lane];
        float2 p0 = __half22float2(*reinterpret_cast<__half2*>(&u0.x));
        float2 p1 = __half22float2(*reinterpret_cast<__half2*>(&u0.y));
        float2 q0 = __half22float2(*reinterpret_cast<__half2*>(&u1.x));
        float2 q1 = __half22float2(*reinterpret_cast<__half2*>(&u1.y));
        a0 += p0.x; a1 += p0.y; a2 += p1.x; a3 += p1.y;
        b0 += q0.x; b1 += q0.y; b2 += q1.x; b3 += q1.y;
    }
    if (j < c) {
        int c0 = g_csr_col[s + j];
        uint2 u0 = f2[(size_t)c0 * 32 + lane];
        float2 p0 = __half22float2(*reinterpret_cast<__half2*>(&u0.x));
        float2 p1 = __half22float2(*reinterpret_cast<__half2*>(&u0.y));
        a0 += p0.x; a1 += p0.y; a2 += p1.x; a3 += p1.y;
    }
    float inv = 1.0f / ((float)c + 1e-8f);
    float4 v = make_float4((a0 + b0) * inv, (a1 + b1) * inv,
                           (a2 + b2) * inv, (a3 + b3) * inv);
    store_h4(r, colb, v);
}

__global__ __launch_bounds__(256) void gather_kernel(
    const float* __restrict__ news) {
    int gw   = (blockIdx.x * blockDim.x + threadIdx.x) >> 5;
    int lane = threadIdx.x & 31;
    if (gw >= N_NEWS) return;
    float4 v = reinterpret_cast<const float4*>(news)[(size_t)gw * 32 + lane];
    store_h4(gw, lane * 4, v);
    agg_part16(g_entf16, g_rowstart[gw], g_deg[gw], gw, 128 + lane * 4, lane);
    agg_part16(g_topf16, g_rowstart[N_NEWS + gw], g_deg[N_NEWS + gw], gw,
               256 + lane * 4, lane);
}

// ==================== GEMM: cp.async 2-stage, K64, fp16xfp16 ===============
// C = act(A @ B^T + bias). A fp16 [M][K]; B fp16 [Ntot][K].
// CTA tile 128x128, K-chunk 64, 8 warps of 64x32. 64KB smem, 2 CTAs/SM.
#define TILE_BYTES 16384
#define STAGE_B    (2 * TILE_BYTES)
#define GEMM_SMEM  (2 * STAGE_B)

template <bool TANH, bool HALF_OUT>
__global__ __launch_bounds__(256, 2) void gemm_mma_kernel(
    const __half* __restrict__ A, const __half* __restrict__ Bh,
    const float* __restrict__ bias,
    float* __restrict__ outF, __half* __restrict__ outH,
    int M, int Ntot, int Kfull) {
    extern __shared__ __align__(1024) char smem[];
    const uint32_t sbase = smem_to_u32(smem);

    const int tid  = threadIdx.x;
    const int wid  = tid >> 5;
    const int lane = tid & 31;
    const int wm   = wid & 1;
    const int wn   = wid >> 1;
    const int m0   = blockIdx.y * 128;
    const int n0   = blockIdx.x * 128;

    float acc[4][4][4] = {};

    const int lrow = tid >> 1;
    const int lseg = (tid & 1) * 4;
    const int gr   = m0 + lrow;
    const int a_ok = gr < M;
    const size_t a_base = (size_t)gr * Kfull + lseg * 8;
    const size_t b_base = (size_t)(n0 + lrow) * Kfull + lseg * 8;

    const int a_row = (lane & 7) + ((lane >> 3) & 1) * 8;
    const int a_ch  = lane >> 4;
    const int b_row = (lane & 7) + ((lane >> 4) & 1) * 8;
    const int b_ch  = (lane >> 3) & 1;

    const int n_chunks = Kfull >> 6;

    auto prefetch = [&](int ch) {
        const int k0 = ch << 6;
        const uint32_t sb = sbase + (ch & 1) * STAGE_B;
        const __half* pa = A + a_base + k0;
        const __half* pb = Bh + b_base + k0;
        #pragma unroll
        for (int s = 0; s < 4; s++) {
            uint32_t so = sw_off(lrow, lseg + s);
            cpa16(sb + so,              pa + s * 8, a_ok);
            cpa16(sb + TILE_BYTES + so, pb + s * 8, 1);
        }
        CP_COMMIT();
    };

    prefetch(0);
    for (int ch = 0; ch < n_chunks; ch++) {
        if (ch + 1 < n_chunks) {
            prefetch(ch + 1);
            CP_WAIT(1);
        } else {
            CP_WAIT(0);
        }
        __syncthreads();

        const uint32_t st = sbase + (ch & 1) * STAGE_B;
        #pragma unroll
        for (int kk = 0; kk < 4; kk++) {
            uint32_t afrag[4][4];
            uint32_t bhf[2][4];
            #pragma unroll
            for (int g2 = 0; g2 < 2; g2++) {
                int nr = wn * 32 + g2 * 16 + b_row;
                ldsm_x4(bhf[g2], st + TILE_BYTES + sw_off(nr, 2 * kk + b_ch));
            }
            #pragma unroll
            for (int mi = 0; mi < 4; mi++) {
                int mr = wm * 64 + mi * 16 + a_row;
                ldsm_x4(afrag[mi], st + sw_off(mr, 2 * kk + a_ch));
            }
            #pragma unroll
            for (int mi = 0; mi < 4; mi++)
                #pragma unroll
                for (int ni = 0; ni < 4; ni++)
                    mma_fp16(acc[mi][ni], afrag[mi],
                             &bhf[ni >> 1][(ni & 1) * 2]);
        }
        __syncthreads();
    }

    const int g = lane >> 2;
    const int q = lane & 3;
    #pragma unroll
    for (int mi = 0; mi < 4; mi++) {
        #pragma unroll
        for (int ni = 0; ni < 4; ni++) {
            int col = n0 + wn * 32 + ni * 8 + q * 2;
            float bia0 = bias[col], bia1 = bias[col + 1];
            #pragma unroll
            for (int half = 0; half < 2; half++) {
                int gm = m0 + wm * 64 + mi * 16 + g + half * 8;
                if (gm >= M) continue;
                float v0 = acc[mi][ni][half * 2 + 0] + bia0;
                float v1 = acc[mi][ni][half * 2 + 1] + bia1;
                if (TANH) { v0 = tanhf(v0); v1 = tanhf(v1); }
                size_t o = (size_t)gm * Ntot + col;
                if (HALF_OUT) {
                    *reinterpret_cast<__half2*>(&outH[o]) =
                        __halves2half2(__float2half_rn(v0), __float2half_rn(v1));
                } else {
                    *reinterpret_cast<float2*>(&outF[o]) = make_float2(v0, v1);
                }
            }
        }
    }
}

// ---------------------------------------------------------------------------
extern "C" void kernel_launch(void* const* d_in, const int* in_sizes, int n_in,
                              void* d_out, int out_size) {
    const float* news    = (const float*)d_in[0];
    const float* entf    = (const float*)d_in[1];
    const float* topf    = (const float*)d_in[2];
    const int*   ent_row = (const int*)d_in[3];
    const int*   ent_col = (const int*)d_in[4];
    const int*   top_row = (const int*)d_in[5];
    const int*   top_col = (const int*)d_in[6];
    const float* W1      = (const float*)d_in[7];
    const float* b1      = (const float*)d_in[8];
    const float* W2      = (const float*)d_in[9];
    const float* b2      = (const float*)d_in[10];
    float* out = (float*)d_out;
    int n_ent = in_sizes[3];
    int n_top = in_sizes[5];

    void *p_x, *p_h, *p_w1, *p_w2;
    cudaGetSymbolAddress(&p_x, g_X);
    cudaGetSymbolAddress(&p_h, g_H);
    cudaGetSymbolAddress(&p_w1, g_W1t);
    cudaGetSymbolAddress(&p_w2, g_W2t);

    cudaFuncSetAttribute(gemm_mma_kernel<true, true>,
                         cudaFuncAttributeMaxDynamicSharedMemorySize, GEMM_SMEM);
    cudaFuncSetAttribute(gemm_mma_kernel<false, false>,
                         cudaFuncAttributeMaxDynamicSharedMemorySize, GEMM_SMEM);

    // launch 1: setup (weight prep + hists + fp16 feature conversion)
    {
        int b1e = (KDIM * HIDN + 255) / 256;
        int b2e = b1e + (HIDN * OUTD + 255) / 256;
        int bhe = b2e + (n_ent + 255) / 256;
        int bte = bhe + (n_top + 255) / 256;
        int bfe = bte + (N_ENT * DIM / 8 + 255) / 256;
        int btot = bfe + (N_TOP * DIM / 8 + 255) / 256;
        setup_kernel<<<btot, 256>>>(W1, W2, ent_row, n_ent, top_row, n_top,
                                    entf, topf, b1e, b2e, bhe, bte, bfe);
    }
    // launches 2-4: parallel scan (exclusive prefix over 200K counters)
    scan1_kernel<<<SCAN_BLOCKS, 256>>>();
    scan2_kernel<<<1, 256>>>(SCAN_BLOCKS);
    scan3_kernel<<<(NTOT2 + 255) / 256, 256>>>();
    // launch 5: fill
    {
        int be = (n_ent + 255) / 256;
        int btot = be + (n_top + 255) / 256;
        fill_both_kernel<<<btot, 256>>>(ent_row, ent_col, n_ent,
                                        top_row, top_col, n_top, be);
    }
    // launch 6: gather -> X (fp16)
    {
        int blocks = (N_NEWS * 32 + 255) / 256;
        gather_kernel<<<blocks, 256>>>(news);
    }

    const int m_tiles = (N_NEWS + 127) / 128;  // 782

    // launch 7: GEMM1  H = tanh(X @ W1 + b1)
    {
        dim3 grid(HIDN / 128, m_tiles);
        gemm_mma_kernel<true, true><<<grid, 256, GEMM_SMEM>>>(
            (const __half*)p_x, (const __half*)p_w1,
            b1, nullptr, (__half*)p_h,
            N_NEWS, HIDN, KDIM);
    }
    // launch 8: GEMM2  out = H @ W2 + b2
    {
        dim3 grid(OUTD / 128, m_tiles);
        gemm_mma_kernel<false, false><<<grid, 256, GEMM_SMEM>>>(
            (const __half*)p_h, (const __half*)p_w2,
            b2, out, nullptr,
            N_NEWS, OUTD, HIDN);
    }
}

// round 14
// speedup vs baseline: 1.5404x; 1.0468x over previous
#include <cuda_runtime.h>
#include <cuda_fp16.h>
#include <cstdint>
#include <cstddef>

#define N_NEWS 100000
#define N_ENT  50000
#define N_TOP  2000
#define DIM    128
#define KDIM   384   // 3*DIM
#define HIDN   512
#define OUTD   128
#define MAX_EDGES 1600000
#define NTOT2  (2 * N_NEWS)
#define SCAN_BLOCKS ((NTOT2 + 1023) / 1024)   // 196

// ---------------- scratch (__device__ globals: allocation-free rule) -------
// g_cnt is zero at module load; scan3 re-zeroes it every run (replay-safe).
__device__ int g_cnt[NTOT2];
__device__ int g_deg[NTOT2];
__device__ int g_rowstart[NTOT2];
__device__ int g_cursor[NTOT2];
__device__ int g_bsum[256];
__device__ int g_csr_col[2 * MAX_EDGES];

__device__ __half g_entf16[(size_t)N_ENT * DIM];
__device__ __half g_topf16[(size_t)N_TOP * DIM];

__device__ __half g_X[(size_t)N_NEWS * KDIM];
__device__ __half g_H[(size_t)N_NEWS * HIDN];
__device__ __half g_W1t[(size_t)HIDN * KDIM];   // [N=512][K=384]
__device__ __half g_W2t[(size_t)OUTD * HIDN];   // [N=128][K=512]

// ---------------- helpers --------------------------------------------------
__device__ __forceinline__ uint32_t smem_to_u32(const void* p) {
    uint32_t a;
    asm("{ .reg .u64 t; cvta.to.shared.u64 t, %1; cvt.u32.u64 %0, t; }"
        : "=r"(a) : "l"(p));
    return a;
}

__device__ __forceinline__ void ldsm_x4(uint32_t* r, uint32_t addr) {
    asm volatile("ldmatrix.sync.aligned.m8n8.x4.shared.b16 {%0,%1,%2,%3}, [%4];"
                 : "=r"(r[0]), "=r"(r[1]), "=r"(r[2]), "=r"(r[3]) : "r"(addr));
}
__device__ __forceinline__ void mma_fp16(float* d, const uint32_t* a,
                                         const uint32_t* b) {
    asm volatile(
        "mma.sync.aligned.m16n8k16.row.col.f32.f16.f16.f32 "
        "{%0,%1,%2,%3}, {%4,%5,%6,%7}, {%8,%9}, {%0,%1,%2,%3};"
        : "+f"(d[0]), "+f"(d[1]), "+f"(d[2]), "+f"(d[3])
        : "r"(a[0]), "r"(a[1]), "r"(a[2]), "r"(a[3]), "r"(b[0]), "r"(b[1]));
}

__device__ __forceinline__ void cpa16(uint32_t s, const void* g, int valid) {
    asm volatile("cp.async.cg.shared.global [%0], [%1], 16, %2;"
                 :: "r"(s), "l"(g), "r"(valid ? 16 : 0) : "memory");
}
#define CP_COMMIT() asm volatile("cp.async.commit_group;" ::: "memory")
#define CP_WAIT(n)  asm volatile("cp.async.wait_group %0;" :: "n"(n) : "memory")

// swizzled byte offset inside a [128 rows x 128B] tile
__device__ __forceinline__ uint32_t sw_off(int row, int chunk16) {
    return (uint32_t)row * 128u + (uint32_t)((chunk16 ^ (row & 7)) << 4);
}

// ==================== launch 1: setup ======================================
__global__ void setup_kernel(const float* __restrict__ W1,
                             const float* __restrict__ W2,
                             const int* __restrict__ ent_row, int n_ent,
                             const int* __restrict__ top_row, int n_top,
                             const float* __restrict__ entf,
                             const float* __restrict__ topf,
                             int b1e, int b2e, int bhe, int bte, int bfe) {
    int b = blockIdx.x;
    if (b < b1e) {
        int idx = b * 256 + threadIdx.x;
        if (idx < KDIM * HIDN) {
            int k = idx / HIDN, n = idx - k * HIDN;
            g_W1t[(size_t)n * KDIM + k] = __float2half_rn(W1[idx]);
        }
    } else if (b < b2e) {
        int idx = (b - b1e) * 256 + threadIdx.x;
        if (idx < HIDN * OUTD) {
            int k = idx / OUTD, n = idx - k * OUTD;
            g_W2t[(size_t)n * HIDN + k] = __float2half_rn(W2[idx]);
        }
    } else if (b < bhe) {
        int i = (b - b2e) * 256 + threadIdx.x;
        if (i < n_ent) atomicAdd(&g_cnt[ent_row[i]], 1);
    } else if (b < bte) {
        int i = (b - bhe) * 256 + threadIdx.x;
        if (i < n_top) atomicAdd(&g_cnt[N_NEWS + top_row[i]], 1);
    } else if (b < bfe) {
        size_t i = ((size_t)(b - bte) * 256 + threadIdx.x) * 8;
        if (i < (size_t)N_ENT * DIM) {
            float4 f0 = *reinterpret_cast<const float4*>(entf + i);
            float4 f1 = *reinterpret_cast<const float4*>(entf + i + 4);
            __half h[8];
            h[0] = __float2half_rn(f0.x); h[1] = __float2half_rn(f0.y);
            h[2] = __float2half_rn(f0.z); h[3] = __float2half_rn(f0.w);
            h[4] = __float2half_rn(f1.x); h[5] = __float2half_rn(f1.y);
            h[6] = __float2half_rn(f1.z); h[7] = __float2half_rn(f1.w);
            *reinterpret_cast<uint4*>(&g_entf16[i]) = *reinterpret_cast<uint4*>(h);
        }
    } else {
        size_t i = ((size_t)(b - bfe) * 256 + threadIdx.x) * 8;
        if (i < (size_t)N_TOP * DIM) {
            float4 f0 = *reinterpret_cast<const float4*>(topf + i);
            float4 f1 = *reinterpret_cast<const float4*>(topf + i + 4);
            __half h[8];
            h[0] = __float2half_rn(f0.x); h[1] = __float2half_rn(f0.y);
            h[2] = __float2half_rn(f0.z); h[3] = __float2half_rn(f0.w);
            h[4] = __float2half_rn(f1.x); h[5] = __float2half_rn(f1.y);
            h[6] = __float2half_rn(f1.z); h[7] = __float2half_rn(f1.w);
            *reinterpret_cast<uint4*>(&g_topf16[i]) = *reinterpret_cast<uint4*>(h);
        }
    }
}

// ==================== launches 2-3: parallel scan ==========================
// scan1: per-block exclusive scan of g_cnt (4 elems/thread), saves deg,
//        writes block sums. 196 blocks x 256 thr.
__global__ void scan1_kernel() {
    __shared__ int sh[256];
    int t = threadIdx.x, b = blockIdx.x;
    int base = b * 1024 + t * 4;
    int v0 = 0, v1 = 0, v2 = 0, v3 = 0;
    if (base + 0 < NTOT2) { v0 = g_cnt[base + 0]; g_deg[base + 0] = v0; }
    if (base + 1 < NTOT2) { v1 = g_cnt[base + 1]; g_deg[base + 1] = v1; }
    if (base + 2 < NTOT2) { v2 = g_cnt[base + 2]; g_deg[base + 2] = v2; }
    if (base + 3 < NTOT2) { v3 = g_cnt[base + 3]; g_deg[base + 3] = v3; }
    sh[t] = v0 + v1 + v2 + v3;
    __syncthreads();
    #pragma unroll
    for (int off = 1; off < 256; off <<= 1) {
        int x = 0;
        if (t >= off) x = sh[t - off];
        __syncthreads();
        if (t >= off) sh[t] += x;
        __syncthreads();
    }
    int run = (t > 0) ? sh[t - 1] : 0;
    if (base + 0 < NTOT2) g_rowstart[base + 0] = run; run += v0;
    if (base + 1 < NTOT2) g_rowstart[base + 1] = run; run += v1;
    if (base + 2 < NTOT2) g_rowstart[base + 2] = run; run += v2;
    if (base + 3 < NTOT2) g_rowstart[base + 3] = run;
    if (t == 255) g_bsum[b] = sh[255];
}

// scan3: each block redundantly prefix-scans the 196 block sums in smem,
// then adds offsets, inits cursors, re-zeroes g_cnt (replay invariant).
__global__ void scan3_kernel() {
    __shared__ int sh[256];
    int t = threadIdx.x;
    int v = (t < SCAN_BLOCKS) ? g_bsum[t] : 0;
    sh[t] = v;
    __syncthreads();
    #pragma unroll
    for (int off = 1; off < 256; off <<= 1) {
        int x = 0;
        if (t >= off) x = sh[t - off];
        __syncthreads();
        if (t >= off) sh[t] += x;
        __syncthreads();
    }
    // exclusive offset for block bb is sh[bb-1]
    int i = blockIdx.x * blockDim.x + t;
    if (i < NTOT2) {
        int bb = i >> 10;
        int off = (bb > 0) ? sh[bb - 1] : 0;
        int r = g_rowstart[i] + off;
        g_rowstart[i] = r;
        g_cursor[i] = r;
        g_cnt[i] = 0;
    }
}

// ==================== launch 4: fill both edge lists =======================
__global__ void fill_both_kernel(const int* __restrict__ ent_row,
                                 const int* __restrict__ ent_col, int n_ent,
                                 const int* __restrict__ top_row,
                                 const int* __restrict__ top_col, int n_top,
                                 int be) {
    int b = blockIdx.x;
    if (b < be) {
        int i = b * 256 + threadIdx.x;
        if (i < n_ent) {
            int p = atomicAdd(&g_cursor[ent_row[i]], 1);
            g_csr_col[p] = ent_col[i];
        }
    } else {
        int i = (b - be) * 256 + threadIdx.x;
        if (i < n_top) {
            int p = atomicAdd(&g_cursor[N_NEWS + top_row[i]], 1);
            g_csr_col[p] = top_col[i];
        }
    }
}

// ==================== launch 5: gather (one warp per news row) =============
__device__ __forceinline__ void store_h4(int r, int colb, float4 v) {
    __half h[4];
    h[0] = __float2half_rn(v.x);
    h[1] = __float2half_rn(v.y);
    h[2] = __float2half_rn(v.z);
    h[3] = __float2half_rn(v.w);
    *reinterpret_cast<uint2*>(&g_X[(size_t)r * KDIM + colb]) =
        *reinterpret_cast<uint2*>(h);
}

__device__ __forceinline__ void agg_part16(const __half* __restrict__ feats,
                                           int s, int c, int r, int colb,
                                           int lane) {
    float a0 = 0.f, a1 = 0.f, a2 = 0.f, a3 = 0.f;
    const uint2* f2 = reinterpret_cast<const uint2*>(feats);
    int j = 0;
    for (; j + 2 <= c; j += 2) {
        int c0 = g_csr_col[s + j];
        int c1 = g_csr_col[s + j + 1];
        uint2 u0 = f2[(size_t)c0 * 32 + lane];
        uint2 u1 = f2[(size_t)c1 * 32 + lane];
        // first-level pairwise add in fp16 (halves the convert+FADD count)
        __half2 s0 = __hadd2(*reinterpret_cast<__half2*>(&u0.x),
                             *reinterpret_cast<__half2*>(&u1.x));
        __half2 s1 = __hadd2(*reinterpret_cast<__half2*>(&u0.y),
                             *reinterpret_cast<__half2*>(&u1.y));
        float2 p0 = __half22float2(s0);
        float2 p1 = __half22float2(s1);
        a0 += p0.x; a1 += p0.y; a2 += p1.x; a3 += p1.y;
    }
    if (j < c) {
        int c0 = g_csr_col[s + j];
        uint2 u0 = f2[(size_t)c0 * 32 + lane];
        float2 p0 = __half22float2(*reinterpret_cast<__half2*>(&u0.x));
        float2 p1 = __half22float2(*reinterpret_cast<__half2*>(&u0.y));
        a0 += p0.x; a1 += p0.y; a2 += p1.x; a3 += p1.y;
    }
    float inv = 1.0f / ((float)c + 1e-8f);
    float4 v = make_float4(a0 * inv, a1 * inv, a2 * inv, a3 * inv);
    store_h4(r, colb, v);
}

__global__ __launch_bounds__(256) void gather_kernel(
    const float* __restrict__ news) {
    int gw   = (blockIdx.x * blockDim.x + threadIdx.x) >> 5;
    int lane = threadIdx.x & 31;
    if (gw >= N_NEWS) return;
    float4 v = reinterpret_cast<const float4*>(news)[(size_t)gw * 32 + lane];
    store_h4(gw, lane * 4, v);
    agg_part16(g_entf16, g_rowstart[gw], g_deg[gw], gw, 128 + lane * 4, lane);
    agg_part16(g_topf16, g_rowstart[N_NEWS + gw], g_deg[N_NEWS + gw], gw,
               256 + lane * 4, lane);
}

// ==================== GEMM: cp.async 2-stage, K64, fp16xfp16 ===============
// C = act(A @ B^T + bias). A fp16 [M][K]; B fp16 [Ntot][K].
// CTA tile 128x128, K-chunk 64, 8 warps of 64x32. 64KB smem, 2 CTAs/SM.
#define TILE_BYTES 16384
#define STAGE_B    (2 * TILE_BYTES)
#define GEMM_SMEM  (2 * STAGE_B)

template <bool TANH, bool HALF_OUT>
__global__ __launch_bounds__(256, 2) void gemm_mma_kernel(
    const __half* __restrict__ A, const __half* __restrict__ Bh,
    const float* __restrict__ bias,
    float* __restrict__ outF, __half* __restrict__ outH,
    int M, int Ntot, int Kfull) {
    extern __shared__ __align__(1024) char smem[];
    const uint32_t sbase = smem_to_u32(smem);

    const int tid  = threadIdx.x;
    const int wid  = tid >> 5;
    const int lane = tid & 31;
    const int wm   = wid & 1;
    const int wn   = wid >> 1;
    const int m0   = blockIdx.y * 128;
    const int n0   = blockIdx.x * 128;

    float acc[4][4][4] = {};

    const int lrow = tid >> 1;
    const int lseg = (tid & 1) * 4;
    const int gr   = m0 + lrow;
    const int a_ok = gr < M;
    const size_t a_base = (size_t)gr * Kfull + lseg * 8;
    const size_t b_base = (size_t)(n0 + lrow) * Kfull + lseg * 8;

    const int a_row = (lane & 7) + ((lane >> 3) & 1) * 8;
    const int a_ch  = lane >> 4;
    const int b_row = (lane & 7) + ((lane >> 4) & 1) * 8;
    const int b_ch  = (lane >> 3) & 1;

    const int n_chunks = Kfull >> 6;

    auto prefetch = [&](int ch) {
        const int k0 = ch << 6;
        const uint32_t sb = sbase + (ch & 1) * STAGE_B;
        const __half* pa = A + a_base + k0;
        const __half* pb = Bh + b_base + k0;
        #pragma unroll
        for (int s = 0; s < 4; s++) {
            uint32_t so = sw_off(lrow, lseg + s);
            cpa16(sb + so,              pa + s * 8, a_ok);
            cpa16(sb + TILE_BYTES + so, pb + s * 8, 1);
        }
        CP_COMMIT();
    };

    prefetch(0);
    for (int ch = 0; ch < n_chunks; ch++) {
        if (ch + 1 < n_chunks) {
            prefetch(ch + 1);
            CP_WAIT(1);
        } else {
            CP_WAIT(0);
        }
        __syncthreads();

        const uint32_t st = sbase + (ch & 1) * STAGE_B;
        #pragma unroll
        for (int kk = 0; kk < 4; kk++) {
            uint32_t afrag[4][4];
            uint32_t bhf[2][4];
            #pragma unroll
            for (int g2 = 0; g2 < 2; g2++) {
                int nr = wn * 32 + g2 * 16 + b_row;
                ldsm_x4(bhf[g2], st + TILE_BYTES + sw_off(nr, 2 * kk + b_ch));
            }
            #pragma unroll
            for (int mi = 0; mi < 4; mi++) {
                int mr = wm * 64 + mi * 16 + a_row;
                ldsm_x4(afrag[mi], st + sw_off(mr, 2 * kk + a_ch));
            }
            #pragma unroll
            for (int mi = 0; mi < 4; mi++)
                #pragma unroll
                for (int ni = 0; ni < 4; ni++)
                    mma_fp16(acc[mi][ni], afrag[mi],
                             &bhf[ni >> 1][(ni & 1) * 2]);
        }
        __syncthreads();
    }

    const int g = lane >> 2;
    const int q = lane & 3;
    #pragma unroll
    for (int mi = 0; mi < 4; mi++) {
        #pragma unroll
        for (int ni = 0; ni < 4; ni++) {
            int col = n0 + wn * 32 + ni * 8 + q * 2;
            float bia0 = bias[col], bia1 = bias[col + 1];
            #pragma unroll
            for (int half = 0; half < 2; half++) {
                int gm = m0 + wm * 64 + mi * 16 + g + half * 8;
                if (gm >= M) continue;
                float v0 = acc[mi][ni][half * 2 + 0] + bia0;
                float v1 = acc[mi][ni][half * 2 + 1] + bia1;
                if (TANH) { v0 = tanhf(v0); v1 = tanhf(v1); }
                size_t o = (size_t)gm * Ntot + col;
                if (HALF_OUT) {
                    *reinterpret_cast<__half2*>(&outH[o]) =
                        __halves2half2(__float2half_rn(v0), __float2half_rn(v1));
                } else {
                    *reinterpret_cast<float2*>(&outF[o]) = make_float2(v0, v1);
                }
            }
        }
    }
}

// ---------------------------------------------------------------------------
extern "C" void kernel_launch(void* const* d_in, const int* in_sizes, int n_in,
                              void* d_out, int out_size) {
    const float* news    = (const float*)d_in[0];
    const float* entf    = (const float*)d_in[1];
    const float* topf    = (const float*)d_in[2];
    const int*   ent_row = (const int*)d_in[3];
    const int*   ent_col = (const int*)d_in[4];
    const int*   top_row = (const int*)d_in[5];
    const int*   top_col = (const int*)d_in[6];
    const float* W1      = (const float*)d_in[7];
    const float* b1      = (const float*)d_in[8];
    const float* W2      = (const float*)d_in[9];
    const float* b2      = (const float*)d_in[10];
    float* out = (float*)d_out;
    int n_ent = in_sizes[3];
    int n_top = in_sizes[5];

    void *p_x, *p_h, *p_w1, *p_w2;
    cudaGetSymbolAddress(&p_x, g_X);
    cudaGetSymbolAddress(&p_h, g_H);
    cudaGetSymbolAddress(&p_w1, g_W1t);
    cudaGetSymbolAddress(&p_w2, g_W2t);

    cudaFuncSetAttribute(gemm_mma_kernel<true, true>,
                         cudaFuncAttributeMaxDynamicSharedMemorySize, GEMM_SMEM);
    cudaFuncSetAttribute(gemm_mma_kernel<false, false>,
                         cudaFuncAttributeMaxDynamicSharedMemorySize, GEMM_SMEM);

    // launch 1: setup (weight prep + hists + fp16 feature conversion)
    {
        int b1e = (KDIM * HIDN + 255) / 256;
        int b2e = b1e + (HIDN * OUTD + 255) / 256;
        int bhe = b2e + (n_ent + 255) / 256;
        int bte = bhe + (n_top + 255) / 256;
        int bfe = bte + (N_ENT * DIM / 8 + 255) / 256;
        int btot = bfe + (N_TOP * DIM / 8 + 255) / 256;
        setup_kernel<<<btot, 256>>>(W1, W2, ent_row, n_ent, top_row, n_top,
                                    entf, topf, b1e, b2e, bhe, bte, bfe);
    }
    // launches 2-3: parallel scan (scan2 folded into scan3)
    scan1_kernel<<<SCAN_BLOCKS, 256>>>();
    scan3_kernel<<<(NTOT2 + 255) / 256, 256>>>();
    // launch 4: fill
    {
        int be = (n_ent + 255) / 256;
        int btot = be + (n_top + 255) / 256;
        fill_both_kernel<<<btot, 256>>>(ent_row, ent_col, n_ent,
                                        top_row, top_col, n_top, be);
    }
    // launch 5: gather -> X (fp16)
    {
        int blocks = (N_NEWS * 32 + 255) / 256;
        gather_kernel<<<blocks, 256>>>(news);
    }

    const int m_tiles = (N_NEWS + 127) / 128;  // 782

    // launch 6: GEMM1  H = tanh(X @ W1 + b1)
    {
        dim3 grid(HIDN / 128, m_tiles);
        gemm_mma_kernel<true, true><<<grid, 256, GEMM_SMEM>>>(
            (const __half*)p_x, (const __half*)p_w1,
            b1, nullptr, (__half*)p_h,
            N_NEWS, HIDN, KDIM);
    }
    // launch 7: GEMM2  out = H @ W2 + b2
    {
        dim3 grid(OUTD / 128, m_tiles);
        gemm_mma_kernel<false, false><<<grid, 256, GEMM_SMEM>>>(
            (const __half*)p_h, (const __half*)p_w2,
            b2, out, nullptr,
            N_NEWS, OUTD, HIDN);
    }
}